// round 9
// baseline (speedup 1.0000x reference)
#include <cuda_runtime.h>
#include <float.h>

#define BT     (16 * 512)   // 8192 pairs
#define IDIM   80
#define HDIM   512
#define NSHIFT 159
#define PAD    79
#define SKP    248
#define SSTR   84           // smem k-stride (conflict-free frag loads)

#define PAIRS_PER_CTA 32
#define NCHUNK 4            // 4 x 128 HDIM columns

// dynamic smem layout (in 4-byte words)
#define OFF_AS 0                         // [32][84] tf32 xattn tile
#define OFF_BS (OFF_AS + 32 * SSTR)      // [128][84] tf32 W chunk
#define OFF_KP (OFF_BS + 128 * SSTR)     // [8][248] keypad per warp
#define OFF_YS (OFF_KP + 8 * SKP)        // [8][80] y per warp
#define SMEM_WORDS (OFF_YS + 8 * IDIM)   // 16064 words = 64256 B

__device__ __forceinline__ float warpReduceSum(float v) {
#pragma unroll
    for (int o = 16; o; o >>= 1) v += __shfl_xor_sync(0xffffffffu, v, o);
    return v;
}
__device__ __forceinline__ float warpReduceMax(float v) {
#pragma unroll
    for (int o = 16; o; o >>= 1) v = fmaxf(v, __shfl_xor_sync(0xffffffffu, v, o));
    return v;
}

__device__ __forceinline__ unsigned f2tf(float f) {
    unsigned r;
    asm("cvt.rna.tf32.f32 %0, %1;" : "=r"(r) : "f"(f));
    return r;
}

__device__ __forceinline__ void mma_tf32(float d[4], const unsigned a[4],
                                         const unsigned b[2]) {
    asm("mma.sync.aligned.m16n8k8.row.col.f32.tf32.tf32.f32 "
        "{%0,%1,%2,%3}, {%4,%5,%6,%7}, {%8,%9}, {%0,%1,%2,%3};"
        : "+f"(d[0]), "+f"(d[1]), "+f"(d[2]), "+f"(d[3])
        : "r"(a[0]), "r"(a[1]), "r"(a[2]), "r"(a[3]), "r"(b[0]), "r"(b[1]));
}

// ---------------------------------------------------------------------------
// Fused kernel: 256 CTAs x 32 pairs.
// Phase A: R6-validated attn (warp-per-pair, 4 reps) -> tf32 As tile in smem.
// Phase B: R8-validated tf32 single-pass mma GEMM, 4 chunks of 128 HDIM cols.
// ---------------------------------------------------------------------------
__global__ __launch_bounds__(256, 2) void fused_kernel(
    const float* __restrict__ x, const float* __restrict__ y,
    const float* __restrict__ W, const float* __restrict__ bias,
    float* __restrict__ out)
{
    extern __shared__ float smem[];
    unsigned* As = reinterpret_cast<unsigned*>(smem + OFF_AS);
    unsigned* Bs = reinterpret_cast<unsigned*>(smem + OFF_BS);

    const int tid  = threadIdx.x;
    const int warp = tid >> 5;
    const int lane = tid & 31;
    float* kpw = smem + OFF_KP + warp * SKP;
    float* ysw = smem + OFF_YS + warp * IDIM;

    // ================= Phase A: attention (4 pairs per warp) ===============
#pragma unroll 1
    for (int rep = 0; rep < 4; ++rep) {
        const int lp = rep * 8 + warp;                       // local pair 0..31
        const int p  = blockIdx.x * PAIRS_PER_CTA + lp;

        for (int i = lane; i < SKP; i += 32) kpw[i] = 0.0f;
        __syncwarp();

        const float* xp = x + (size_t)p * IDIM;
        const float* yp = y + (size_t)p * IDIM;
        float yn2 = 0.0f;
        for (int i = lane; i < IDIM; i += 32) {
            kpw[PAD + i] = xp[i];
            float v = yp[i];
            ysw[i] = v;
            yn2 = fmaf(v, v, yn2);
        }
        yn2 = warpReduceSum(yn2);
        __syncwarp();

        const int base = lane * 5;
        float w0 = kpw[base + 0], w1 = kpw[base + 1], w2 = kpw[base + 2],
              w3 = kpw[base + 3], w4 = kpw[base + 4];
        const float i0 = w0, i1 = w1, i2 = w2, i3 = w3;

        float d0 = 0, d1 = 0, d2 = 0, d3 = 0, d4 = 0, core = 0;
#pragma unroll
        for (int i = 0; i < IDIM; ++i) {
            float yv = ysw[i];
            d0 = fmaf(w0, yv, d0);
            d1 = fmaf(w1, yv, d1);
            d2 = fmaf(w2, yv, d2);
            d3 = fmaf(w3, yv, d3);
            d4 = fmaf(w4, yv, d4);
            if (i < IDIM - 4) core = fmaf(w4, w4, core);
            w0 = w1; w1 = w2; w2 = w3; w3 = w4;
            w4 = kpw[base + 5 + i];
        }

        const float t0 = kpw[base + 80], t1 = kpw[base + 81],
                    t2 = kpw[base + 82], t3 = kpw[base + 83];
        const float H3 = i3 * i3;
        const float H2 = fmaf(i2, i2, H3);
        const float H1 = fmaf(i1, i1, H2);
        const float H0 = fmaf(i0, i0, H1);
        const float T1 = t0 * t0;
        const float T2 = fmaf(t1, t1, T1);
        const float T3 = fmaf(t2, t2, T2);
        const float T4 = fmaf(t3, t3, T3);

        float dotv[5] = {d0, d1, d2, d3, d4};
        float n2v[5];
        n2v[0] = H0 + core;
        n2v[1] = (H1 + core) + T1;
        n2v[2] = (H2 + core) + T2;
        n2v[3] = (H3 + core) + T3;
        n2v[4] = core + T4;

        const float yn = sqrtf(yn2);
        float best = -FLT_MAX;
        int   bidx = 0;
#pragma unroll
        for (int j = 0; j < 5; ++j) {
            int s = base + j;
            if (s < NSHIFT) {
                float den = sqrtf(n2v[j]) * yn;
                float sim = (den > 0.0f) ? (dotv[j] / den) : 0.0f;
                if (sim > best) { best = sim; bidx = s; }
            }
        }
#pragma unroll
        for (int o = 16; o; o >>= 1) {
            float ov = __shfl_xor_sync(0xffffffffu, best, o);
            int   oi = __shfl_xor_sync(0xffffffffu, bidx, o);
            if (ov > best || (ov == best && oi < bidx)) { best = ov; bidx = oi; }
        }
        const int bs = bidx;

        float xa[3], sc[3];
        float m = -FLT_MAX;
#pragma unroll
        for (int t = 0; t < 3; ++t) {
            int i = lane + t * 32;
            if (i < IDIM) {
                xa[t] = kpw[bs + i];
                sc[t] = xa[t] * ysw[i];
                m = fmaxf(m, sc[t]);
            }
        }
        m = warpReduceMax(m);
        float sum = 0.0f, e[3];
#pragma unroll
        for (int t = 0; t < 3; ++t) {
            int i = lane + t * 32;
            if (i < IDIM) { e[t] = expf((sc[t] - m) * 0.1f); sum += e[t]; }
        }
        sum = warpReduceSum(sum);
        const float inv = 1.0f / sum;
#pragma unroll
        for (int t = 0; t < 3; ++t) {
            int i = lane + t * 32;
            if (i < IDIM) As[lp * SSTR + i] = f2tf(xa[t] * (e[t] * inv));
        }
    }

    // ================= Phase B: GEMM out[32p x 512h] = As @ W^T + b ========
    const int wm = warp >> 2;       // 0..1  (16 pair-rows each)
    const int wn = warp & 3;        // 0..3  (32 cols each)
    const int g  = lane >> 2;
    const int t  = lane & 3;
    const int bp = blockIdx.x * PAIRS_PER_CTA;

#pragma unroll 1
    for (int chunk = 0; chunk < NCHUNK; ++chunk) {
        const int bn = chunk * 128;
        __syncthreads();   // As ready (first iter) / prior Bs reads done

        // Fill Bs: 128 rows x 20 float4 (2560 / 256 threads = 10 each)
#pragma unroll
        for (int it = 0; it < 10; ++it) {
            int idx = tid + it * 256;
            int row = idx / 20;
            int k4  = (idx % 20) * 4;
            float4 b = *reinterpret_cast<const float4*>(
                W + (size_t)(bn + row) * IDIM + k4);
            uint4 tb = make_uint4(f2tf(b.x), f2tf(b.y), f2tf(b.z), f2tf(b.w));
            *reinterpret_cast<uint4*>(&Bs[row * SSTR + k4]) = tb;
        }
        __syncthreads();

        float d[4][4];
#pragma unroll
        for (int nt = 0; nt < 4; ++nt)
#pragma unroll
            for (int r = 0; r < 4; ++r) d[nt][r] = 0.0f;

#pragma unroll
        for (int k0 = 0; k0 < IDIM; k0 += 8) {
            unsigned af[4];
            {
                int r0 = (wm * 16 + g) * SSTR + k0 + t;
                af[0] = As[r0];
                af[1] = As[r0 + 8 * SSTR];
                af[2] = As[r0 + 4];
                af[3] = As[r0 + 8 * SSTR + 4];
            }
#pragma unroll
            for (int nt = 0; nt < 4; ++nt) {
                unsigned bf[2];
                int nr = (wn * 32 + nt * 8 + g) * SSTR + k0 + t;
                bf[0] = Bs[nr];
                bf[1] = Bs[nr + 4];
                mma_tf32(d[nt], af, bf);
            }
        }

        // Epilogue: c0,c1 -> (row, 2t..2t+1); c2,c3 -> (row+8, 2t..2t+1)
#pragma unroll
        for (int nt = 0; nt < 4; ++nt) {
            int row = bp + wm * 16 + g;
            int col = bn + wn * 32 + nt * 8 + 2 * t;
            float b0 = __ldg(bias + col), b1 = __ldg(bias + col + 1);
            float2 o0 = make_float2(d[nt][0] + b0, d[nt][1] + b1);
            float2 o1 = make_float2(d[nt][2] + b0, d[nt][3] + b1);
            *reinterpret_cast<float2*>(out + (size_t)row * HDIM + col) = o0;
            *reinterpret_cast<float2*>(out + (size_t)(row + 8) * HDIM + col) = o1;
        }
    }
}

extern "C" void kernel_launch(void* const* d_in, const int* in_sizes, int n_in,
                              void* d_out, int out_size)
{
    const float* x    = (const float*)d_in[0];
    const float* y    = (const float*)d_in[1];
    const float* fc1w = (const float*)d_in[2];
    const float* fc1b = (const float*)d_in[3];
    float* out = (float*)d_out;

    const int smem_bytes = SMEM_WORDS * (int)sizeof(float);   // 64256
    cudaFuncSetAttribute(fused_kernel,
                         cudaFuncAttributeMaxDynamicSharedMemorySize, smem_bytes);
    fused_kernel<<<BT / PAIRS_PER_CTA, 256, smem_bytes>>>(x, y, fc1w, fc1b, out);
}